// round 3
// baseline (speedup 1.0000x reference)
#include <cuda_runtime.h>
#include <math.h>

#define BB 16
#define SS 96
#define TT 50
#define NR 1536          // B*S
#define NHID 1537        // rows of "hidden"
#define HID 128
#define G4 512           // 4*H
#define D2 256
#define G3 768           // 3*D2
#define GW 1536          // Gi(768) | Gh(768)

// ---------------- scratch (device globals; no allocations) ----------------
__device__ float g_Xg[2][NR * TT * G4];   // precomputed x@Wih.T + b, per dir (~315MB)
__device__ float g_hT[2][NR * HID];
__device__ float g_cT[2][NR * HID];
__device__ float g_hidA[NHID * D2];
__device__ float g_hidB[NHID * D2];
__device__ float g_G[NHID * GW];          // [Gi | Gh] per row

__device__ __forceinline__ float sigf(float x) { return 1.f / (1.f + __expf(-x)); }
__device__ __forceinline__ float tanhfast(float x) {
    float t = __expf(2.f * x);
    return 1.f - 2.f / (t + 1.f);         // robust at +-inf
}
__device__ __forceinline__ float dot4(float4 a, float4 b) {
    return a.x * b.x + a.y * b.y + a.z * b.z + a.w * b.w;
}

// ---------------------------------------------------------------------------
// Kernel 1: Xgates = gather(emb_table, enc) @ Wih^T + b, for both directions.
// M = 76800 (n*50+t), K = 128, N = 512. Tiled 64x64, BK=64, 4x4 micro-tile.
// ---------------------------------------------------------------------------
__global__ void __launch_bounds__(256) xgates_kernel(
    const int* __restrict__ enc, const float* __restrict__ emb,
    const float* __restrict__ Wf, const float* __restrict__ bf,
    const float* __restrict__ Wb, const float* __restrict__ bb)
{
    __shared__ __align__(16) float As[64][68];   // transposed: As[k][m]
    __shared__ __align__(16) float Ws[64][68];   // transposed: Ws[k][n]
    __shared__ int rows[64];

    const int dir = blockIdx.z;
    const float* __restrict__ W = dir ? Wb : Wf;
    const float* __restrict__ bias = dir ? bb : bf;
    const int mb = blockIdx.x * 64;
    const int nb = blockIdx.y * 64;
    const int tid = threadIdx.x;
    const int tx = tid & 15, ty = tid >> 4;

    if (tid < 64) rows[tid] = enc[mb + tid];
    __syncthreads();

    float acc[4][4];
#pragma unroll
    for (int j = 0; j < 4; j++) {
        float bv = __ldg(&bias[nb + tx * 4 + j]);
#pragma unroll
        for (int i = 0; i < 4; i++) acc[i][j] = bv;
    }

    for (int k0 = 0; k0 < 128; k0 += 64) {
        for (int x = tid; x < 4096; x += 256) {
            int mm = x >> 6, kk = x & 63;
            As[kk][mm] = emb[(size_t)rows[mm] * 128 + k0 + kk];
        }
        for (int x = tid; x < 4096; x += 256) {
            int nn = x >> 6, kk = x & 63;
            Ws[kk][nn] = W[(nb + nn) * 128 + k0 + kk];
        }
        __syncthreads();
#pragma unroll 8
        for (int kk = 0; kk < 64; kk++) {
            float4 a = *(const float4*)&As[kk][ty * 4];
            float4 w = *(const float4*)&Ws[kk][tx * 4];
            acc[0][0] += a.x * w.x; acc[0][1] += a.x * w.y; acc[0][2] += a.x * w.z; acc[0][3] += a.x * w.w;
            acc[1][0] += a.y * w.x; acc[1][1] += a.y * w.y; acc[1][2] += a.y * w.z; acc[1][3] += a.y * w.w;
            acc[2][0] += a.z * w.x; acc[2][1] += a.z * w.y; acc[2][2] += a.z * w.z; acc[2][3] += a.z * w.w;
            acc[3][0] += a.w * w.x; acc[3][1] += a.w * w.y; acc[3][2] += a.w * w.z; acc[3][3] += a.w * w.w;
        }
        __syncthreads();
    }
#pragma unroll
    for (int i = 0; i < 4; i++)
#pragma unroll
        for (int j = 0; j < 4; j++)
            g_Xg[dir][(size_t)(mb + ty * 4 + i) * G4 + nb + tx * 4 + j] = acc[i][j];
}

// ---------------------------------------------------------------------------
// Kernel 2: LSTM recurrence. Rows are independent -> no inter-block sync.
// Block = 256 threads handles 16 rows for one direction; thread t owns gate
// rows t and t+256; h/c/gates live in smem; Whh streamed (L1-resident-ish).
// ---------------------------------------------------------------------------
#define LROWS 16
__global__ void __launch_bounds__(256) lstm_kernel(
    const float* __restrict__ Whh_f, const float* __restrict__ Whh_b)
{
    const int dir = blockIdx.y;
    const int rowBase = blockIdx.x * LROWS;
    const float* __restrict__ W = dir ? Whh_b : Whh_f;
    const float* __restrict__ Xg = g_Xg[dir];
    const int tid = threadIdx.x;
    const int j0 = tid, j1 = tid + 256;

    __shared__ __align__(16) float hs[LROWS][128];
    __shared__ __align__(16) float cs[LROWS][128];
    __shared__ float gs[LROWS][512];

    for (int e = tid; e < LROWS * 128; e += 256) {
        ((float*)hs)[e] = 0.f; ((float*)cs)[e] = 0.f;
    }
    __syncthreads();

#pragma unroll 1
    for (int t = 0; t < TT; t++) {
        const int te = dir ? (TT - 1 - t) : t;
        float acc0[LROWS], acc1[LROWS];
#pragma unroll
        for (int r = 0; r < LROWS; r++) {
            size_t base = ((size_t)(rowBase + r) * TT + te) * G4;
            acc0[r] = Xg[base + j0];
            acc1[r] = Xg[base + j1];
        }
#pragma unroll 2
        for (int kc = 0; kc < 128; kc += 16) {
            float4 w0[4], w1[4];
            const float4* p0 = reinterpret_cast<const float4*>(&W[j0 * 128 + kc]);
            const float4* p1 = reinterpret_cast<const float4*>(&W[j1 * 128 + kc]);
#pragma unroll
            for (int q = 0; q < 4; q++) { w0[q] = __ldg(p0 + q); w1[q] = __ldg(p1 + q); }
#pragma unroll
            for (int r = 0; r < LROWS; r++) {
                const float4* hp = reinterpret_cast<const float4*>(&hs[r][kc]);
#pragma unroll
                for (int q = 0; q < 4; q++) {
                    float4 h4 = hp[q];
                    acc0[r] += dot4(w0[q], h4);
                    acc1[r] += dot4(w1[q], h4);
                }
            }
        }
#pragma unroll
        for (int r = 0; r < LROWS; r++) { gs[r][j0] = acc0[r]; gs[r][j1] = acc1[r]; }
        __syncthreads();
        for (int e = tid; e < LROWS * 128; e += 256) {
            int r = e >> 7, ch = e & 127;
            float gi = gs[r][ch], gf = gs[r][128 + ch];
            float gg = gs[r][256 + ch], go = gs[r][384 + ch];
            float c = sigf(gf) * cs[r][ch] + sigf(gi) * tanhfast(gg);
            float h = sigf(go) * tanhfast(c);
            cs[r][ch] = c; hs[r][ch] = h;
        }
        __syncthreads();
    }
    for (int e = tid; e < LROWS * 128; e += 256) {
        int r = e >> 7, ch = e & 127;
        int n = rowBase + r;
        g_hT[dir][n * HID + ch] = hs[r][ch];
        g_cT[dir][n * HID + ch] = cs[r][ch];
    }
}

// ---------------------------------------------------------------------------
// Kernel 3: hidden[1537,256]: row0 = 0; rows 1..1536:
//   [ relu([cf|cb]@Wc^T+bc) | relu([hf|hb]@Whr^T+bhr) ]  -> g_hidA
// ---------------------------------------------------------------------------
__global__ void __launch_bounds__(256) reduce_kernel(
    const float* __restrict__ Wc, const float* __restrict__ bc,
    const float* __restrict__ Whr, const float* __restrict__ bhr)
{
    const int nb = blockIdx.x * 8;
    const int tid = threadIdx.x;
    __shared__ __align__(16) float inA[8][256];  // [cf|cb]
    __shared__ __align__(16) float inB[8][256];  // [hf|hb]
    for (int x = tid; x < 8 * 256; x += 256) {
        int r = x >> 8, k = x & 255;
        int n = nb + r;
        inA[r][k] = (k < 128) ? g_cT[0][n * HID + k] : g_cT[1][n * HID + (k - 128)];
        inB[r][k] = (k < 128) ? g_hT[0][n * HID + k] : g_hT[1][n * HID + (k - 128)];
    }
    __syncthreads();

    const bool isC = tid < 128;
    const float* __restrict__ Wrow = isC ? (Wc + tid * 256) : (Whr + (tid - 128) * 256);
    const float bias = isC ? __ldg(&bc[tid]) : __ldg(&bhr[tid - 128]);
    const float (*IN)[256] = isC ? inA : inB;

    float acc[8];
#pragma unroll
    for (int r = 0; r < 8; r++) acc[r] = bias;
#pragma unroll 4
    for (int k = 0; k < 256; k += 16) {
        float4 w[4];
        const float4* wp = reinterpret_cast<const float4*>(Wrow + k);
#pragma unroll
        for (int q = 0; q < 4; q++) w[q] = __ldg(wp + q);
#pragma unroll
        for (int r = 0; r < 8; r++) {
            const float4* ip = reinterpret_cast<const float4*>(&IN[r][k]);
#pragma unroll
            for (int q = 0; q < 4; q++) acc[r] += dot4(w[q], ip[q]);
        }
    }
#pragma unroll
    for (int r = 0; r < 8; r++)
        g_hidA[(nb + r + 1) * D2 + tid] = fmaxf(acc[r], 0.f);
    if (blockIdx.x == 0) g_hidA[tid] = 0.f;   // zero row
}

// ---------------------------------------------------------------------------
// Kernel 4: G = [ hidden@Wi^T+bi | hidden@Wh^T+bh ], M=1537, N=1536, K=256.
// ---------------------------------------------------------------------------
__global__ void __launch_bounds__(256) gates_gemm(
    int srcSel,
    const float* __restrict__ Wi, const float* __restrict__ Wh,
    const float* __restrict__ bi, const float* __restrict__ bh)
{
    __shared__ __align__(16) float As[64][68];
    __shared__ __align__(16) float Ws[64][68];
    const float* __restrict__ A = srcSel ? g_hidB : g_hidA;
    const int mb = blockIdx.x * 64;
    const int nb = blockIdx.y * 64;
    const int tid = threadIdx.x;
    const int tx = tid & 15, ty = tid >> 4;
    const bool half = (nb >= G3);
    const float* __restrict__ W = half ? Wh : Wi;
    const float* __restrict__ bias = half ? bh : bi;
    const int nw = half ? nb - G3 : nb;

    float acc[4][4];
#pragma unroll
    for (int j = 0; j < 4; j++) {
        float bv = __ldg(&bias[nw + tx * 4 + j]);
#pragma unroll
        for (int i = 0; i < 4; i++) acc[i][j] = bv;
    }
    for (int k0 = 0; k0 < 256; k0 += 64) {
        for (int x = tid; x < 4096; x += 256) {
            int mm = x >> 6, kk = x & 63;
            int m = mb + mm;
            As[kk][mm] = (m < NHID) ? A[m * D2 + k0 + kk] : 0.f;
        }
        for (int x = tid; x < 4096; x += 256) {
            int nn = x >> 6, kk = x & 63;
            Ws[kk][nn] = W[(nw + nn) * D2 + k0 + kk];
        }
        __syncthreads();
#pragma unroll 8
        for (int kk = 0; kk < 64; kk++) {
            float4 a = *(const float4*)&As[kk][ty * 4];
            float4 w = *(const float4*)&Ws[kk][tx * 4];
            acc[0][0] += a.x * w.x; acc[0][1] += a.x * w.y; acc[0][2] += a.x * w.z; acc[0][3] += a.x * w.w;
            acc[1][0] += a.y * w.x; acc[1][1] += a.y * w.y; acc[1][2] += a.y * w.z; acc[1][3] += a.y * w.w;
            acc[2][0] += a.z * w.x; acc[2][1] += a.z * w.y; acc[2][2] += a.z * w.z; acc[2][3] += a.z * w.w;
            acc[3][0] += a.w * w.x; acc[3][1] += a.w * w.y; acc[3][2] += a.w * w.z; acc[3][3] += a.w * w.w;
        }
        __syncthreads();
    }
#pragma unroll
    for (int i = 0; i < 4; i++) {
        int m = mb + ty * 4 + i;
        if (m < NHID) {
#pragma unroll
            for (int j = 0; j < 4; j++)
                g_G[(size_t)m * GW + nb + tx * 4 + j] = acc[i][j];
        }
    }
}

// ---------------------------------------------------------------------------
// Kernel 5: GRU + masked sum + norm-scaled residual update.
// One block per output row (b,q); thread d owns dim d. Deterministic order.
// phase 0 (cp): sum over i at fixed (b,j): x=child, h=parent
// phase 1 (pc): sum over j at fixed (b,i): x=parent, h=child
// ---------------------------------------------------------------------------
__global__ void __launch_bounds__(256) gru_kernel(
    int srcSel, int dstSel, float* __restrict__ extDst,
    const int* __restrict__ sp, const int* __restrict__ sc,
    const float* __restrict__ mask, int phase)
{
    const float* __restrict__ hid = srcSel ? g_hidB : g_hidA;
    float* __restrict__ dst = (dstSel == 2) ? extDst : (dstSel ? g_hidB : g_hidA);
    const int o = blockIdx.x;          // 0..1535
    const int b = o / SS, q = o % SS;
    const int d = threadIdx.x;         // 0..255
    if (o == 0) dst[d] = hid[d];       // keep zero row

    float acc = 0.f;
    for (int u = 0; u < SS; u++) {
        int idx = (phase == 0) ? ((b * SS + u) * SS + q) : ((b * SS + q) * SS + u);
        float mv = __ldg(&mask[idx]);
        if (mv == 0.f) continue;
        int par = __ldg(&sp[idx]);
        int chi = __ldg(&sc[idx]);
        int xr = (phase == 0) ? chi : par;   // Gi row (x input)
        int hr = (phase == 0) ? par : chi;   // Gh row + h row
        const float* __restrict__ gi = g_G + (size_t)xr * GW;
        const float* __restrict__ gh = g_G + (size_t)hr * GW + G3;
        float r = sigf(gi[d] + gh[d]);
        float z = sigf(gi[256 + d] + gh[256 + d]);
        float n = tanhfast(gi[512 + d] + r * gh[512 + d]);
        float hv = hid[hr * D2 + d];
        acc += mv * ((1.f - z) * n + z * hv);
    }
    __shared__ float sm[256];
    sm[d] = acc * acc;
    __syncthreads();
    for (int s = 128; s > 0; s >>= 1) {
        if (d < s) sm[d] += sm[d + s];
        __syncthreads();
    }
    float v = sqrtf(sm[0]);
    float scale = (v + 0.25f) / (v + 1.f);
    dst[(o + 1) * D2 + d] = hid[(o + 1) * D2 + d] + acc * scale;
}

// ---------------------------------------------------------------------------
extern "C" void kernel_launch(void* const* d_in, const int* in_sizes, int n_in,
                              void* d_out, int out_size)
{
    const int*   enc    = (const int*)  d_in[0];
    const int*   sp     = (const int*)  d_in[1];
    const int*   sc     = (const int*)  d_in[2];
    const float* mask   = (const float*)d_in[3];
    const float* emb    = (const float*)d_in[4];
    const float* Wih_f  = (const float*)d_in[5];
    const float* Whh_f  = (const float*)d_in[6];
    const float* b_f    = (const float*)d_in[7];
    const float* Wih_b  = (const float*)d_in[8];
    const float* Whh_b  = (const float*)d_in[9];
    const float* b_b    = (const float*)d_in[10];
    const float* Wc     = (const float*)d_in[11];
    const float* bc     = (const float*)d_in[12];
    const float* Whr    = (const float*)d_in[13];
    const float* bhr    = (const float*)d_in[14];
    const float* Wi_cp  = (const float*)d_in[15];
    const float* Wh_cp  = (const float*)d_in[16];
    const float* bi_cp  = (const float*)d_in[17];
    const float* bh_cp  = (const float*)d_in[18];
    const float* Wi_pc  = (const float*)d_in[19];
    const float* Wh_pc  = (const float*)d_in[20];
    const float* bi_pc  = (const float*)d_in[21];
    const float* bh_pc  = (const float*)d_in[22];
    float* out = (float*)d_out;
    (void)in_sizes; (void)n_in; (void)out_size;

    // 1) x-side LSTM gates for both directions (time-parallel GEMM + gather)
    xgates_kernel<<<dim3(NR * TT / 64, G4 / 64, 2), 256>>>(enc, emb, Wih_f, b_f, Wih_b, b_b);

    // 2) recurrent LSTM, fwd+bwd concurrently (rows independent)
    lstm_kernel<<<dim3(NR / LROWS, 2), 256>>>(Whh_f, Whh_b);

    // 3) build hidden (g_hidA)
    reduce_kernel<<<NR / 8, 256>>>(Wc, bc, Whr, bhr);

    // 4) 2x cp + 2x pc GRU structure updates, ping-pong A->B->A->B->out
    for (int it = 0; it < 4; it++) {
        int phase  = it >> 1;
        int srcSel = it & 1;                // 0:A 1:B
        int dstSel = (it == 3) ? 2 : (1 - (it & 1));
        const float* Wi = phase ? Wi_pc : Wi_cp;
        const float* Wh = phase ? Wh_pc : Wh_cp;
        const float* bi = phase ? bi_pc : bi_cp;
        const float* bh = phase ? bh_pc : bh_cp;
        gates_gemm<<<dim3((NHID + 63) / 64, GW / 64), 256>>>(srcSel, Wi, Wh, bi, bh);
        gru_kernel<<<NR, 256>>>(srcSel, dstSel, out, sp, sc, mask, phase);
    }
}

// round 4
// speedup vs baseline: 1.2507x; 1.2507x over previous
#include <cuda_runtime.h>
#include <math.h>

#define BB 16
#define SS 96
#define TT 50
#define NR 1536          // B*S
#define NHID 1537        // rows of "hidden"
#define HID 128
#define G4 512           // 4*H
#define D2 256
#define G3 768           // 3*D2
#define GW 1536          // Gi(768) | Gh(768)
#define VSZ 32000

// ---------------- scratch (device globals; no allocations) ----------------
__device__ float g_Evoc[2][(size_t)VSZ * G4];  // emb_table @ Wih^T + b, per dir (131MB)
__device__ float g_hT[2][NR * HID];
__device__ float g_cT[2][NR * HID];
__device__ float g_hidA[NHID * D2];
__device__ float g_hidB[NHID * D2];
__device__ float g_G[NHID * GW];               // [Gi | Gh] per row

__device__ __forceinline__ float sigf(float x) { return 1.f / (1.f + __expf(-x)); }
__device__ __forceinline__ float tanhfast(float x) {
    float t = __expf(2.f * x);
    return 1.f - 2.f / (t + 1.f);
}
__device__ __forceinline__ float dot4(float4 a, float4 b) {
    return a.x * b.x + a.y * b.y + a.z * b.z + a.w * b.w;
}

// ---------------------------------------------------------------------------
// Kernel 1: Evoc[dir] = emb_table @ W^T + b.  M=32000, N=512, K=128.
// 128x128 tile, 256 threads, 8x8 micro-tile, BK=16. Smem transposed [k][m].
// ---------------------------------------------------------------------------
__global__ void __launch_bounds__(256) evoc_kernel(
    const float* __restrict__ emb,
    const float* __restrict__ Wf, const float* __restrict__ bf,
    const float* __restrict__ Wb, const float* __restrict__ bb)
{
    __shared__ __align__(16) float As[16][132];
    __shared__ __align__(16) float Bs[16][132];

    const int dir = blockIdx.z;
    const float* __restrict__ W = dir ? Wb : Wf;
    const float* __restrict__ bias = dir ? bb : bf;
    float* __restrict__ C = g_Evoc[dir];

    const int mb = blockIdx.x * 128;
    const int nb = blockIdx.y * 128;
    const int tid = threadIdx.x;
    const int tx = tid & 15, ty = tid >> 4;

    float acc[8][8];
#pragma unroll
    for (int j = 0; j < 8; j++) {
        float bv = __ldg(&bias[nb + tx * 8 + j]);
#pragma unroll
        for (int i = 0; i < 8; i++) acc[i][j] = bv;
    }

    for (int k0 = 0; k0 < 128; k0 += 16) {
#pragma unroll
        for (int l = 0; l < 2; l++) {
            int f = tid * 2 + l;            // 0..511
            int m = f >> 2, kq = (f & 3) * 4;
            float4 v = *(const float4*)&emb[(size_t)(mb + m) * 128 + k0 + kq];
            As[kq + 0][m] = v.x; As[kq + 1][m] = v.y; As[kq + 2][m] = v.z; As[kq + 3][m] = v.w;
            float4 w = *(const float4*)&W[(size_t)(nb + m) * 128 + k0 + kq];
            Bs[kq + 0][m] = w.x; Bs[kq + 1][m] = w.y; Bs[kq + 2][m] = w.z; Bs[kq + 3][m] = w.w;
        }
        __syncthreads();
#pragma unroll
        for (int kk = 0; kk < 16; kk++) {
            float4 a0 = *(const float4*)&As[kk][ty * 8];
            float4 a1 = *(const float4*)&As[kk][ty * 8 + 4];
            float4 b0 = *(const float4*)&Bs[kk][tx * 8];
            float4 b1 = *(const float4*)&Bs[kk][tx * 8 + 4];
            float av[8] = {a0.x,a0.y,a0.z,a0.w,a1.x,a1.y,a1.z,a1.w};
            float bv[8] = {b0.x,b0.y,b0.z,b0.w,b1.x,b1.y,b1.z,b1.w};
#pragma unroll
            for (int i = 0; i < 8; i++)
#pragma unroll
                for (int j = 0; j < 8; j++)
                    acc[i][j] += av[i] * bv[j];
        }
        __syncthreads();
    }
#pragma unroll
    for (int i = 0; i < 8; i++) {
        size_t row = (size_t)(mb + ty * 8 + i) * G4 + nb + tx * 8;
        float4 o0 = {acc[i][0], acc[i][1], acc[i][2], acc[i][3]};
        float4 o1 = {acc[i][4], acc[i][5], acc[i][6], acc[i][7]};
        *(float4*)&C[row] = o0;
        *(float4*)&C[row + 4] = o1;
    }
}

// ---------------------------------------------------------------------------
// Kernel 2: LSTM recurrence, gathering x-gates from Evoc by token id.
// Block = 256 threads, LROWS rows, one direction. Thread owns gate rows
// tid and tid+256. h/c/gates in smem; Whh streamed from L2.
// ---------------------------------------------------------------------------
#define LROWS 12
__global__ void __launch_bounds__(256) lstm_kernel(
    const int* __restrict__ enc,
    const float* __restrict__ Whh_f, const float* __restrict__ Whh_b)
{
    const int dir = blockIdx.y;
    const int rowBase = blockIdx.x * LROWS;
    const float* __restrict__ W = dir ? Whh_b : Whh_f;
    const float* __restrict__ Ev = g_Evoc[dir];
    const int tid = threadIdx.x;
    const int j0 = tid, j1 = tid + 256;

    __shared__ __align__(16) float hs[LROWS][128];
    __shared__ __align__(16) float cs[LROWS][128];
    __shared__ float gs[LROWS][512];
    __shared__ int toks[LROWS * TT];

    for (int e = tid; e < LROWS * 128; e += 256) {
        ((float*)hs)[e] = 0.f; ((float*)cs)[e] = 0.f;
    }
    for (int x = tid; x < LROWS * TT; x += 256)
        toks[x] = enc[(rowBase + x / TT) * TT + (x % TT)];
    __syncthreads();

#pragma unroll 1
    for (int t = 0; t < TT; t++) {
        const int te = dir ? (TT - 1 - t) : t;
        float acc0[LROWS], acc1[LROWS];
#pragma unroll
        for (int r = 0; r < LROWS; r++) {
            const float* ev = Ev + (size_t)toks[r * TT + te] * G4;
            acc0[r] = __ldg(&ev[j0]);
            acc1[r] = __ldg(&ev[j1]);
        }
#pragma unroll 2
        for (int kc = 0; kc < 128; kc += 16) {
            float4 w0[4], w1[4];
            const float4* p0 = reinterpret_cast<const float4*>(&W[j0 * 128 + kc]);
            const float4* p1 = reinterpret_cast<const float4*>(&W[j1 * 128 + kc]);
#pragma unroll
            for (int q = 0; q < 4; q++) { w0[q] = __ldg(p0 + q); w1[q] = __ldg(p1 + q); }
#pragma unroll
            for (int r = 0; r < LROWS; r++) {
                const float4* hp = reinterpret_cast<const float4*>(&hs[r][kc]);
#pragma unroll
                for (int q = 0; q < 4; q++) {
                    float4 h4 = hp[q];
                    acc0[r] += dot4(w0[q], h4);
                    acc1[r] += dot4(w1[q], h4);
                }
            }
        }
#pragma unroll
        for (int r = 0; r < LROWS; r++) { gs[r][j0] = acc0[r]; gs[r][j1] = acc1[r]; }
        __syncthreads();
        for (int e = tid; e < LROWS * 128; e += 256) {
            int r = e >> 7, ch = e & 127;
            float gi = gs[r][ch], gf = gs[r][128 + ch];
            float gg = gs[r][256 + ch], go = gs[r][384 + ch];
            float c = sigf(gf) * cs[r][ch] + sigf(gi) * tanhfast(gg);
            float h = sigf(go) * tanhfast(c);
            cs[r][ch] = c; hs[r][ch] = h;
        }
        __syncthreads();
    }
    for (int e = tid; e < LROWS * 128; e += 256) {
        int r = e >> 7, ch = e & 127;
        int n = rowBase + r;
        g_hT[dir][n * HID + ch] = hs[r][ch];
        g_cT[dir][n * HID + ch] = cs[r][ch];
    }
}

// ---------------------------------------------------------------------------
// Kernel 3: hidden rows 1..1536 = [relu([cf|cb]@Wc^T+bc) | relu([hf|hb]@Whr^T+bhr)]
// ---------------------------------------------------------------------------
__global__ void __launch_bounds__(256) reduce_kernel(
    const float* __restrict__ Wc, const float* __restrict__ bc,
    const float* __restrict__ Whr, const float* __restrict__ bhr)
{
    const int nb = blockIdx.x * 8;
    const int tid = threadIdx.x;
    __shared__ __align__(16) float inA[8][256];
    __shared__ __align__(16) float inB[8][256];
    for (int x = tid; x < 8 * 256; x += 256) {
        int r = x >> 8, k = x & 255;
        int n = nb + r;
        inA[r][k] = (k < 128) ? g_cT[0][n * HID + k] : g_cT[1][n * HID + (k - 128)];
        inB[r][k] = (k < 128) ? g_hT[0][n * HID + k] : g_hT[1][n * HID + (k - 128)];
    }
    __syncthreads();

    const bool isC = tid < 128;
    const float* __restrict__ Wrow = isC ? (Wc + tid * 256) : (Whr + (tid - 128) * 256);
    const float bias = isC ? __ldg(&bc[tid]) : __ldg(&bhr[tid - 128]);
    const float (*IN)[256] = isC ? inA : inB;

    float acc[8];
#pragma unroll
    for (int r = 0; r < 8; r++) acc[r] = bias;
#pragma unroll 4
    for (int k = 0; k < 256; k += 16) {
        float4 w[4];
        const float4* wp = reinterpret_cast<const float4*>(Wrow + k);
#pragma unroll
        for (int q = 0; q < 4; q++) w[q] = __ldg(wp + q);
#pragma unroll
        for (int r = 0; r < 8; r++) {
            const float4* ip = reinterpret_cast<const float4*>(&IN[r][k]);
#pragma unroll
            for (int q = 0; q < 4; q++) acc[r] += dot4(w[q], ip[q]);
        }
    }
#pragma unroll
    for (int r = 0; r < 8; r++)
        g_hidA[(nb + r + 1) * D2 + tid] = fmaxf(acc[r], 0.f);
    if (blockIdx.x == 0) g_hidA[tid] = 0.f;
}

// ---------------------------------------------------------------------------
// Kernel 4: G = [hidden@Wi^T+bi | hidden@Wh^T+bh], M=1537, N=1536, K=256.
// 128x128 tile, 8x8 micro-tile, BK=16.
// ---------------------------------------------------------------------------
__global__ void __launch_bounds__(256) gates_gemm(
    int srcSel,
    const float* __restrict__ Wi, const float* __restrict__ Wh,
    const float* __restrict__ bi, const float* __restrict__ bh)
{
    __shared__ __align__(16) float As[16][132];
    __shared__ __align__(16) float Bs[16][132];
    const float* __restrict__ A = srcSel ? g_hidB : g_hidA;
    const int mb = blockIdx.x * 128;
    const int nb = blockIdx.y * 128;
    const int tid = threadIdx.x;
    const int tx = tid & 15, ty = tid >> 4;
    const bool half = (nb >= G3);
    const float* __restrict__ W = half ? Wh : Wi;
    const float* __restrict__ bias = half ? bh : bi;
    const int nw = half ? nb - G3 : nb;

    float acc[8][8];
#pragma unroll
    for (int j = 0; j < 8; j++) {
        float bv = __ldg(&bias[nw + tx * 8 + j]);
#pragma unroll
        for (int i = 0; i < 8; i++) acc[i][j] = bv;
    }

    for (int k0 = 0; k0 < 256; k0 += 16) {
#pragma unroll
        for (int l = 0; l < 2; l++) {
            int f = tid * 2 + l;
            int m = f >> 2, kq = (f & 3) * 4;
            int mg = mb + m;
            float4 v = (mg < NHID) ? *(const float4*)&A[(size_t)mg * D2 + k0 + kq]
                                   : make_float4(0.f, 0.f, 0.f, 0.f);
            As[kq + 0][m] = v.x; As[kq + 1][m] = v.y; As[kq + 2][m] = v.z; As[kq + 3][m] = v.w;
            float4 w = *(const float4*)&W[(size_t)(nw + m) * D2 + k0 + kq];
            Bs[kq + 0][m] = w.x; Bs[kq + 1][m] = w.y; Bs[kq + 2][m] = w.z; Bs[kq + 3][m] = w.w;
        }
        __syncthreads();
#pragma unroll
        for (int kk = 0; kk < 16; kk++) {
            float4 a0 = *(const float4*)&As[kk][ty * 8];
            float4 a1 = *(const float4*)&As[kk][ty * 8 + 4];
            float4 b0 = *(const float4*)&Bs[kk][tx * 8];
            float4 b1 = *(const float4*)&Bs[kk][tx * 8 + 4];
            float av[8] = {a0.x,a0.y,a0.z,a0.w,a1.x,a1.y,a1.z,a1.w};
            float bv[8] = {b0.x,b0.y,b0.z,b0.w,b1.x,b1.y,b1.z,b1.w};
#pragma unroll
            for (int i = 0; i < 8; i++)
#pragma unroll
                for (int j = 0; j < 8; j++)
                    acc[i][j] += av[i] * bv[j];
        }
        __syncthreads();
    }
#pragma unroll
    for (int i = 0; i < 8; i++) {
        int m = mb + ty * 8 + i;
        if (m < NHID) {
            size_t row = (size_t)m * GW + nb + tx * 8;
            float4 o0 = {acc[i][0], acc[i][1], acc[i][2], acc[i][3]};
            float4 o1 = {acc[i][4], acc[i][5], acc[i][6], acc[i][7]};
            *(float4*)&g_G[row] = o0;
            *(float4*)&g_G[row + 4] = o1;
        }
    }
}

// ---------------------------------------------------------------------------
// Kernel 5: GRU + masked sum + norm-scaled residual update.
// ---------------------------------------------------------------------------
__global__ void __launch_bounds__(256) gru_kernel(
    int srcSel, int dstSel, float* __restrict__ extDst,
    const int* __restrict__ sp, const int* __restrict__ sc,
    const float* __restrict__ mask, int phase)
{
    const float* __restrict__ hid = srcSel ? g_hidB : g_hidA;
    float* __restrict__ dst = (dstSel == 2) ? extDst : (dstSel ? g_hidB : g_hidA);
    const int o = blockIdx.x;
    const int b = o / SS, q = o % SS;
    const int d = threadIdx.x;
    if (o == 0) dst[d] = hid[d];

    float acc = 0.f;
    for (int u = 0; u < SS; u++) {
        int idx = (phase == 0) ? ((b * SS + u) * SS + q) : ((b * SS + q) * SS + u);
        float mv = __ldg(&mask[idx]);
        if (mv == 0.f) continue;
        int par = __ldg(&sp[idx]);
        int chi = __ldg(&sc[idx]);
        int xr = (phase == 0) ? chi : par;
        int hr = (phase == 0) ? par : chi;
        const float* __restrict__ gi = g_G + (size_t)xr * GW;
        const float* __restrict__ gh = g_G + (size_t)hr * GW + G3;
        float r = sigf(gi[d] + gh[d]);
        float z = sigf(gi[256 + d] + gh[256 + d]);
        float n = tanhfast(gi[512 + d] + r * gh[512 + d]);
        float hv = hid[hr * D2 + d];
        acc += mv * ((1.f - z) * n + z * hv);
    }
    __shared__ float sm[256];
    sm[d] = acc * acc;
    __syncthreads();
    for (int s = 128; s > 0; s >>= 1) {
        if (d < s) sm[d] += sm[d + s];
        __syncthreads();
    }
    float v = sqrtf(sm[0]);
    float scale = (v + 0.25f) / (v + 1.f);
    dst[(o + 1) * D2 + d] = hid[(o + 1) * D2 + d] + acc * scale;
}

// ---------------------------------------------------------------------------
extern "C" void kernel_launch(void* const* d_in, const int* in_sizes, int n_in,
                              void* d_out, int out_size)
{
    const int*   enc    = (const int*)  d_in[0];
    const int*   sp     = (const int*)  d_in[1];
    const int*   sc     = (const int*)  d_in[2];
    const float* mask   = (const float*)d_in[3];
    const float* emb    = (const float*)d_in[4];
    const float* Wih_f  = (const float*)d_in[5];
    const float* Whh_f  = (const float*)d_in[6];
    const float* b_f    = (const float*)d_in[7];
    const float* Wih_b  = (const float*)d_in[8];
    const float* Whh_b  = (const float*)d_in[9];
    const float* b_b    = (const float*)d_in[10];
    const float* Wc     = (const float*)d_in[11];
    const float* bc     = (const float*)d_in[12];
    const float* Whr    = (const float*)d_in[13];
    const float* bhr    = (const float*)d_in[14];
    const float* Wi_cp  = (const float*)d_in[15];
    const float* Wh_cp  = (const float*)d_in[16];
    const float* bi_cp  = (const float*)d_in[17];
    const float* bh_cp  = (const float*)d_in[18];
    const float* Wi_pc  = (const float*)d_in[19];
    const float* Wh_pc  = (const float*)d_in[20];
    const float* bi_pc  = (const float*)d_in[21];
    const float* bh_pc  = (const float*)d_in[22];
    float* out = (float*)d_out;
    (void)in_sizes; (void)n_in; (void)out_size;

    // 1) vocab-side x-gates: Evoc = emb_table @ Wih^T + b (2.4x fewer FLOPs
    //    than per-token, kills the 315MB scratch round-trip)
    evoc_kernel<<<dim3(VSZ / 128, G4 / 128, 2), 256>>>(emb, Wih_f, b_f, Wih_b, b_b);

    // 2) recurrent LSTM, fwd+bwd concurrently (rows independent)
    lstm_kernel<<<dim3(NR / LROWS, 2), 256>>>(enc, Whh_f, Whh_b);

    // 3) build hidden (g_hidA)
    reduce_kernel<<<NR / 8, 256>>>(Wc, bc, Whr, bhr);

    // 4) 2x cp + 2x pc GRU structure updates, ping-pong A->B->A->B->out
    for (int it = 0; it < 4; it++) {
        int phase  = it >> 1;
        int srcSel = it & 1;
        int dstSel = (it == 3) ? 2 : (1 - (it & 1));
        const float* Wi = phase ? Wi_pc : Wi_cp;
        const float* Wh = phase ? Wh_pc : Wh_cp;
        const float* bi = phase ? bi_pc : bi_cp;
        const float* bh = phase ? bh_pc : bh_cp;
        gates_gemm<<<dim3((NHID + 127) / 128, GW / 128), 256>>>(srcSel, Wi, Wh, bi, bh);
        gru_kernel<<<NR, 256>>>(srcSel, dstSel, out, sp, sc, mask, phase);
    }
}